// round 15
// baseline (speedup 1.0000x reference)
#include <cuda_runtime.h>
#include <cstdint>
#include <math.h>

// Problem constants
#define B_   64
#define T_   4096
#define D_   128
#define H_   256
#define G_   768   // 3*H
#define C_   128

__device__ float g_hfinal[B_ * H_];

// Dynamic SMEM layout for gru_scan (float offsets)
#define OFF_HP    0        // hPf  [2][1024]
#define OFF_PART  2048     // part [2][3072]
#define OFF_IHP   8192     // ihp  [3][1536]
#define OFF_XS    12800    // x_s  [3][512]
#define OFF_WIH   14336    // wih  [96][132]  (pad 132: 16B-aligned rows, 4-wf LDS.128)
#define OFF_MBAR_BYTES 108032
#define SMEM_SCAN 108160

// Packed fp32x2 FMA (Blackwell)
#define FFMA2(acc, a, b) \
    asm("fma.rn.f32x2 %0, %1, %2, %0;" : "+l"(acc) : "l"(a), "l"(b))

__device__ __forceinline__ float2 unpack2(unsigned long long v) {
    float2 f;
    asm("mov.b64 {%0, %1}, %2;" : "=f"(f.x), "=f"(f.y) : "l"(v));
    return f;
}

// ---------------------------------------------------------------------------
// Cluster / DSMEM / mbarrier helpers
// ---------------------------------------------------------------------------
__device__ __forceinline__ uint32_t smem_u32(const void* p) {
    uint32_t a;
    asm("{ .reg .u64 t; cvta.to.shared.u64 t, %1; cvt.u32.u64 %0, t; }"
        : "=r"(a) : "l"(p));
    return a;
}
__device__ __forceinline__ uint32_t mapa_u32(uint32_t a, uint32_t rank) {
    uint32_t r;
    asm("mapa.shared::cluster.u32 %0, %1, %2;" : "=r"(r) : "r"(a), "r"(rank));
    return r;
}
__device__ __forceinline__ uint32_t ctarank() {
    uint32_t r;
    asm("mov.u32 %0, %%cluster_ctarank;" : "=r"(r));
    return r;
}
#define CLUSTER_SYNC() do { \
    asm volatile("barrier.cluster.arrive.aligned;" ::: "memory"); \
    asm volatile("barrier.cluster.wait.aligned;"   ::: "memory"); \
} while (0)

#define MBAR_INIT(a, c) \
    asm volatile("mbarrier.init.shared.b64 [%0], %1;" :: "r"(a), "r"(c) : "memory")
#define MBAR_EXPECT_TX(a, tx) \
    asm volatile("mbarrier.arrive.expect_tx.shared.b64 _, [%0], %1;" :: "r"(a), "r"(tx) : "memory")

#define ST_ASYNC_V4(addr, x, y, z, w, mbar) \
    asm volatile("st.async.shared::cluster.mbarrier::complete_tx::bytes.v4.b32 [%0], {%1,%2,%3,%4}, [%5];" \
                 :: "r"(addr), "r"(__float_as_uint(x)), "r"(__float_as_uint(y)), \
                    "r"(__float_as_uint(z)), "r"(__float_as_uint(w)), "r"(mbar) : "memory")

__device__ __forceinline__ void mbar_wait(uint32_t addr, uint32_t phase) {
    uint32_t done;
    asm volatile(
        "{\n\t.reg .pred p;\n\t"
        "mbarrier.try_wait.parity.acquire.cta.shared::cta.b64 p, [%1], %2;\n\t"
        "selp.b32 %0, 1, 0, p;\n\t}"
        : "=r"(done) : "r"(addr), "r"(phase) : "memory");
    while (!done) {
        asm volatile(
            "{\n\t.reg .pred p;\n\t"
            "mbarrier.try_wait.parity.acquire.cta.shared::cta.b64 p, [%1], %2, 0x989680;\n\t"
            "selp.b32 %0, 1, 0, p;\n\t}"
            : "=r"(done) : "r"(addr), "r"(phase) : "memory");
    }
}

// MUFU-based activations (ex2/rcp approx: rel err ~2^-22)
__device__ __forceinline__ float fast_sigmoid(float x) {
    float e, r;
    asm("ex2.approx.f32 %0, %1;" : "=f"(e) : "f"(x * -1.442695040888963f));
    asm("rcp.approx.f32 %0, %1;" : "=f"(r) : "f"(1.f + e));
    return r;
}
__device__ __forceinline__ float fast_tanh(float x) {
    float e, r;
    asm("ex2.approx.f32 %0, %1;" : "=f"(e) : "f"(x * -2.885390081777927f));
    asm("rcp.approx.f32 %0, %1;" : "=f"(r) : "f"(1.f + e));
    return fmaf(2.f, r, -1.f);
}

// ---------------------------------------------------------------------------
// Fused GRU: R6/R13 scan structure + igates produced in the producer-warp
// shadow (warps 4..15 compute ih partials for step t+1 after bar.arrive 2,
// while they would otherwise idle in their mbar-wait). No separate GEMM.
// All new sync is intra-CTA; %3 buffering on ihp/x_s is causally protected
// by the two-hop send chain (see analysis); x-slab STS->read ordered by
// bar.sync 4 (384 threads = warps 4..15).
// ---------------------------------------------------------------------------
__global__ __launch_bounds__(768, 1) void gru_scan(
    const float* __restrict__ X,      // [B, T, D]
    const float* __restrict__ Whh,    // [G, H]
    const float* __restrict__ Wih,    // [G, D]
    const float* __restrict__ bias3h, // [G]
    const float* __restrict__ bn_g)   // [H]
{
    extern __shared__ __align__(16) float smf[];
    float* hPf  = smf + OFF_HP;
    float* part = smf + OFF_PART;
    float* ihp  = smf + OFF_IHP;
    float* x_s  = smf + OFF_XS;
    float* wih  = smf + OFF_WIH;

    const int tid   = threadIdx.x;
    const uint32_t crank = ctarank();
    const int bbase = (blockIdx.x >> 3) * 4;

    const int warp = tid >> 5, lane = tid & 31;
    const int kc = warp / 3;                 // k-chunk / source 0..7
    const int r  = (warp % 3) * 32 + lane;   // local row 0..95
    const int grow = (r >> 5) * 256 + (int)crank * 32 + (r & 31);

    // hh weights in registers (f32x2 k-pairs)
    unsigned long long w2[16];
    {
        const ulonglong2* wr = reinterpret_cast<const ulonglong2*>(
            Whh + (size_t)grow * H_ + kc * 32);
#pragma unroll
        for (int i = 0; i < 8; i++) { ulonglong2 v = wr[i]; w2[2*i] = v.x; w2[2*i+1] = v.y; }
    }

    // ih weights into SMEM: thread (kc, r) copies cols [kc*16, kc*16+16)
    {
        const float* gsrc = Wih + (size_t)grow * D_ + kc * 16;
        float* dst = wih + r * 132 + kc * 16;
#pragma unroll
        for (int i = 0; i < 16; i += 4) *(float4*)(dst + i) = *(const float4*)(gsrc + i);
    }

    const uint32_t hP_base   = smem_u32(smf) + OFF_HP * 4;
    const uint32_t mbar_base = smem_u32(smf) + OFF_MBAR_BYTES;
    const uint32_t my_wait   = mbar_base + (uint32_t)kc * 8;

    // Gating thread (tid<128)
    const int gbm = tid >> 5, gj = tid & 31;
    float bnv = 0.f, hreg = 0.f, br = 0.f, bz = 0.f, bnn = 0.f;
    if (tid < 128) {
        const int g = (int)crank * 32 + gj;
        bnv = bn_g[g];
        br  = bias3h[g];
        bz  = bias3h[256 + g];
        bnn = bias3h[512 + g];
    }

    // Send setup (gating lanes)
    uint32_t send_a0 = 0, send_a1 = 0, send_m0 = 0, send_m1 = 0;
    if (tid < 128) {
        const uint32_t c  = (uint32_t)(gj >> 2);
        const uint32_t d0 = (uint32_t)(gj & 3), d1 = d0 + 4;
        uint32_t base = hP_base + (uint32_t)crank * 512 + (uint32_t)gbm * 128 + c * 16;
        send_a0 = mapa_u32(base, d0);
        send_a1 = mapa_u32(base, d1);
        send_m0 = mapa_u32(mbar_base + (uint32_t)crank * 8, d0);
        send_m1 = mapa_u32(mbar_base + (uint32_t)crank * 8, d1);
    }

    // x staging (warps 4..7: 128 threads, one float4 each covers [4bm][128])
    const int xi   = tid - 128;
    const int xoff = ((xi >> 5) * 128 + (xi & 31) * 4);
    const float* xsrc = X + ((size_t)(bbase + ((xi >> 5) & 3)) * T_) * D_ + (xi & 31) * 4;

    // ih compute mapping (warps 4..15): dc = D-chunk of 32, r2 = row
    const int pw = warp - 4;
    const int dc = (pw >= 0) ? (pw / 3) : 0;           // 0..3 valid for warps 4..15
    const int r2 = (pw >= 0) ? ((pw % 3) * 32 + lane) : 0;

    auto ih_compute = [&](int slab) {
        const ulonglong2* wp = reinterpret_cast<const ulonglong2*>(wih + r2 * 132 + dc * 32);
#pragma unroll
        for (int bm = 0; bm < 4; bm++) {
            const ulonglong2* xp = reinterpret_cast<const ulonglong2*>(
                x_s + slab * 512 + bm * 128 + dc * 32);
            unsigned long long acc = 0ull;
#pragma unroll
            for (int i = 0; i < 8; i++) {
                ulonglong2 wv = wp[i];
                ulonglong2 u  = xp[i];
                FFMA2(acc, wv.x, u.x);
                FFMA2(acc, wv.y, u.y);
            }
            float2 f = unpack2(acc);
            ihp[slab * 1536 + dc * 384 + bm * 96 + r2] = f.x + f.y;
        }
    };

    // Init: x slab 0, barriers, zero h buffer 0
    if (warp >= 4 && warp < 8) {
        float4 v = *(const float4*)(xsrc);           // x[.., t=0, ..]
        *(float4*)(x_s + xoff) = v;
    }
    if (tid < 16) MBAR_INIT(mbar_base + tid * 8, 1);
    __syncthreads();
    if (tid < 8) MBAR_EXPECT_TX(mbar_base + 64 + tid * 8, 512);
    for (int i = tid; i < 1024; i += 768) hPf[i] = 0.f;
    if (warp >= 4 && warp < 16) ih_compute(0);       // ihp[0] for t=0
    __syncthreads();
    CLUSTER_SYNC();   // barriers + zeros + ihp[0] visible before any sends

    int s = 0;  // == t % 3
    for (int t = 0; t < T_; t++) {
        if (t) { s++; if (s == 3) s = 0; }
        const int buf = t & 1;
        const uint32_t phase = (uint32_t)(((t >> 1) + (buf ^ 1)) & 1);

        // Stage x[t+1] (warps 4..7) — consumed in this step's shadow
        float4 xreg = make_float4(0.f, 0.f, 0.f, 0.f);
        if (warp >= 4 && warp < 8 && t + 1 < T_)
            xreg = *(const float4*)(xsrc + (size_t)(t + 1) * D_);

        // Wait only for this warp's source block
        if (t > 0) mbar_wait(my_wait + (uint32_t)buf * 64, phase);

        // hh matvec: per c-iter 4x LDS.128 + 8 FFMA2
        unsigned long long a0 = 0ull, a1 = 0ull, a2 = 0ull, a3 = 0ull;
        {
            const ulonglong2* hv = reinterpret_cast<const ulonglong2*>(
                hPf + buf * 1024 + kc * 128);
#pragma unroll
            for (int c = 0; c < 8; c++) {
                ulonglong2 u0 = hv[c];
                ulonglong2 u1 = hv[8 + c];
                ulonglong2 u2 = hv[16 + c];
                ulonglong2 u3 = hv[24 + c];
                FFMA2(a0, w2[2*c], u0.x); FFMA2(a0, w2[2*c+1], u0.y);
                FFMA2(a1, w2[2*c], u1.x); FFMA2(a1, w2[2*c+1], u1.y);
                FFMA2(a2, w2[2*c], u2.x); FFMA2(a2, w2[2*c+1], u2.y);
                FFMA2(a3, w2[2*c], u3.x); FFMA2(a3, w2[2*c+1], u3.y);
            }
        }
        {
            float2 f0 = unpack2(a0), f1 = unpack2(a1), f2 = unpack2(a2), f3 = unpack2(a3);
            float* pb = part + buf * 3072 + kc * 384;
            pb[      r] = f0.x + f0.y;   // conflict-free: bank = lane
            pb[ 96 + r] = f1.x + f1.y;
            pb[192 + r] = f2.x + f2.y;
            pb[288 + r] = f3.x + f3.y;
        }

        if (warp >= 4) {
            asm volatile("bar.arrive 2, 768;" ::: "memory");
            // Shadow: produce igates for t+1 (warps 4..15), hidden in wait slack
            if (warp < 16 && t + 1 < T_) {
                const int sn = (s == 2) ? 0 : s + 1;   // (t+1) % 3
                if (warp < 8) *(float4*)(x_s + sn * 512 + xoff) = xreg;
                asm volatile("bar.sync 4, 384;" ::: "memory");
                ih_compute(sn);
            }
            continue;
        }

        // Gating warps: wait for all partials
        asm volatile("bar.sync 2, 768;" ::: "memory");

        // Re-arm barriers[buf] for step t+2 BEFORE our sends (causal gating)
        if (tid < 8) MBAR_EXPECT_TX(mbar_base + (uint32_t)buf * 64 + (uint32_t)tid * 8, 512);

        // Reduce hh partials (8-way) and ih partials (4-way) + bias
        float hr = 0.f, hz = 0.f, hn = 0.f;
        {
            const float* pb = part + buf * 3072 + gbm * 96 + gj;
#pragma unroll
            for (int q = 0; q < 8; q++) {
                hr += pb[q * 384];
                hz += pb[q * 384 + 32];
                hn += pb[q * 384 + 64];
            }
        }
        float ir = br, iz = bz, inn = bnn;
        {
            const float* qb = ihp + s * 1536 + gbm * 96 + gj;
#pragma unroll
            for (int q = 0; q < 4; q++) {
                ir  += qb[q * 384];
                iz  += qb[q * 384 + 32];
                inn += qb[q * 384 + 64];
            }
        }
        float rr = fast_sigmoid(ir + hr);
        float zz = fast_sigmoid(iz + hz);
        float nn = fast_tanh(inn + rr * (hn + bnv));
        hreg = nn + zz * (hreg - nn);

        if (t == T_ - 1) {
            g_hfinal[(bbase + gbm) * H_ + (int)crank * 32 + gj] = hreg;
        } else {
            const int qb2 = gj & ~3;
            float v0 = __shfl_sync(0xffffffffu, hreg, qb2 + 0);
            float v1 = __shfl_sync(0xffffffffu, hreg, qb2 + 1);
            float v2 = __shfl_sync(0xffffffffu, hreg, qb2 + 2);
            float v3 = __shfl_sync(0xffffffffu, hreg, qb2 + 3);
            const uint32_t off = (uint32_t)(buf ^ 1) * 4096;
            const uint32_t mof = (uint32_t)(buf ^ 1) * 64;
            ST_ASYNC_V4(send_a0 + off, v0, v1, v2, v3, send_m0 + mof);
            ST_ASYNC_V4(send_a1 + off, v0, v1, v2, v3, send_m1 + mof);
        }
    }

    CLUSTER_SYNC();  // no CTA exits while peers' inbound stores may reference it
}

// ---------------------------------------------------------------------------
// Kernel 3: out = h_final @ w_proj^T + b_proj
// ---------------------------------------------------------------------------
__global__ __launch_bounds__(128) void proj_kernel(
    const float* __restrict__ Wp,
    const float* __restrict__ bp,
    float* __restrict__ out)
{
    __shared__ float hs[H_];
    int b = blockIdx.x;
    for (int k = threadIdx.x; k < H_; k += 128) hs[k] = g_hfinal[b * H_ + k];
    __syncthreads();
    int c = threadIdx.x;
    float acc = bp[c];
    const float* wr = Wp + (size_t)c * H_;
#pragma unroll 8
    for (int k = 0; k < H_; k++) acc = fmaf(hs[k], wr[k], acc);
    out[b * C_ + c] = acc;
}

// ---------------------------------------------------------------------------
// Launch: single fused scan (no GEMM) + projection. Serial, one stream.
// ---------------------------------------------------------------------------
extern "C" void kernel_launch(void* const* d_in, const int* in_sizes, int n_in,
                              void* d_out, int out_size)
{
    const float* x      = (const float*)d_in[0];
    const float* w_ih   = (const float*)d_in[1];
    const float* w_hh   = (const float*)d_in[2];
    const float* b      = (const float*)d_in[3];
    const float* bn     = (const float*)d_in[4];
    const float* w_proj = (const float*)d_in[5];
    const float* b_proj = (const float*)d_in[6];
    float* out = (float*)d_out;

    cudaFuncSetAttribute(gru_scan, cudaFuncAttributeMaxDynamicSharedMemorySize,
                         SMEM_SCAN);

    {
        cudaLaunchConfig_t cfg = {};
        cfg.gridDim  = dim3(128, 1, 1);
        cfg.blockDim = dim3(768, 1, 1);
        cfg.dynamicSmemBytes = SMEM_SCAN;
        cfg.stream = 0;
        cudaLaunchAttribute attr[1];
        attr[0].id = cudaLaunchAttributeClusterDimension;
        attr[0].val.clusterDim.x = 8;
        attr[0].val.clusterDim.y = 1;
        attr[0].val.clusterDim.z = 1;
        cfg.attrs = attr;
        cfg.numAttrs = 1;
        cudaLaunchKernelEx(&cfg, gru_scan, x, w_hh, w_ih, b, bn);
    }

    proj_kernel<<<B_, 128>>>(w_proj, b_proj, out);
}

// round 16
// speedup vs baseline: 1.6733x; 1.6733x over previous
#include <cuda_runtime.h>
#include <cstdint>
#include <math.h>

// Problem constants
#define B_   64
#define T_   4096
#define D_   128
#define H_   256
#define G_   768   // 3*H
#define C_   128

__device__ float g_igates[(size_t)T_ * B_ * G_];
__device__ float g_hfinal[B_ * H_];

// Packed fp32x2 FMA (Blackwell)
#define FFMA2(acc, a, b) \
    asm("fma.rn.f32x2 %0, %1, %2, %0;" : "+l"(acc) : "l"(a), "l"(b))

__device__ __forceinline__ float2 unpack2(unsigned long long v) {
    float2 f;
    asm("mov.b64 {%0, %1}, %2;" : "=f"(f.x), "=f"(f.y) : "l"(v));
    return f;
}

// ---------------------------------------------------------------------------
// Kernel 1: igates = x @ w_ih^T + b   (f32x2 sgemm, 128x128x16 tiles)
// Single-buffered (occupancy-preserving: 24KB smem, ~106 regs) with the A
// operand PRE-DUPLICATED in SMEM: As2[k][m*2]==As2[k][m*2+1]==A[m][k].
// A reads are ty-indexed (16 lanes share ty) -> 4 LDS.128 broadcasts,
// conflict-free, and the 8 PACK movs per k-step disappear.
// ---------------------------------------------------------------------------
__global__ __launch_bounds__(256) void igates_gemm(
    const float* __restrict__ X,
    const float* __restrict__ W,
    const float* __restrict__ bias)
{
    __shared__ __align__(16) float As2[16][256];  // A duplicated along m
    __shared__ __align__(16) float Bs[16][128];

    const int tid = threadIdx.x;
    const int mb  = blockIdx.x * 128;
    const int nb  = blockIdx.y * 128;
    const int tx  = tid & 15;
    const int ty  = tid >> 4;
    const int lq  = tid & 3;
    const int lm  = tid >> 2;

    unsigned long long acc2[4][8];   // [m-pair][n]
#pragma unroll
    for (int i = 0; i < 4; i++)
#pragma unroll
        for (int j = 0; j < 8; j++) acc2[i][j] = 0ull;

    const float* Xp0 = X + (size_t)(mb + lm) * D_ + 4 * lq;
    const float* Xp1 = Xp0 + (size_t)64 * D_;
    const float* Wp0 = W + (size_t)(nb + lm) * D_ + 4 * lq;
    const float* Wp1 = Wp0 + (size_t)64 * D_;

#pragma unroll
    for (int kt = 0; kt < D_; kt += 16) {
        float4 a0 = *(const float4*)(Xp0 + kt);
        float4 a1 = *(const float4*)(Xp1 + kt);
        float4 b0 = *(const float4*)(Wp0 + kt);
        float4 b1 = *(const float4*)(Wp1 + kt);
        __syncthreads();
        {
            float av0[4] = {a0.x, a0.y, a0.z, a0.w};
            float av1[4] = {a1.x, a1.y, a1.z, a1.w};
            float bv0[4] = {b0.x, b0.y, b0.z, b0.w};
            float bv1[4] = {b1.x, b1.y, b1.z, b1.w};
#pragma unroll
            for (int q = 0; q < 4; q++) {
                As2[4*lq+q][lm*2]        = av0[q];
                As2[4*lq+q][lm*2+1]      = av0[q];
                As2[4*lq+q][(lm+64)*2]   = av1[q];
                As2[4*lq+q][(lm+64)*2+1] = av1[q];
                Bs[4*lq+q][lm]           = bv0[q];
                Bs[4*lq+q][lm+64]        = bv1[q];
            }
        }
        __syncthreads();
#pragma unroll
        for (int k = 0; k < 16; k++) {
            unsigned long long aa2[4];   // duplicated m-pairs (broadcast reads)
            unsigned long long bb2[4];   // n-pairs
            {
                ulonglong2 r0 = *(const ulonglong2*)&As2[k][ty * 16 + 0];
                ulonglong2 r1 = *(const ulonglong2*)&As2[k][ty * 16 + 4];
                ulonglong2 r2 = *(const ulonglong2*)&As2[k][ty * 16 + 8];
                ulonglong2 r3 = *(const ulonglong2*)&As2[k][ty * 16 + 12];
                // r0.x = (a0,a0), r0.y = (a1,a1), ... NOT what we need per-FMA;
                // each 16B = {a_{2q},a_{2q},a_{2q+1},a_{2q+1}}: .x=(a2q,a2q),
                // .y=(a2q+1,a2q+1) -> splat pairs, one per m index.
                aa2[0] = r0.x;  // m = ty*8+0 splat  (use .y for +1 below)
                aa2[1] = r1.x;
                aa2[2] = r2.x;
                aa2[3] = r3.x;
                unsigned long long ao[4] = {r0.y, r1.y, r2.y, r3.y};
                {
                    ulonglong2 q0 = *(const ulonglong2*)&Bs[k][tx * 8];
                    ulonglong2 q1 = *(const ulonglong2*)&Bs[k][tx * 8 + 4];
                    bb2[0] = q0.x; bb2[1] = q0.y; bb2[2] = q1.x; bb2[3] = q1.y;
                }
                // acc2[i][j]: i = m-pair index {0..3} covers m=2i (even) via aa2,
                // j<4 -> even-m rows; j>=4 -> odd-m rows (ao).
#pragma unroll
                for (int i = 0; i < 4; i++) {
                    FFMA2(acc2[i][0], aa2[i], bb2[0]);
                    FFMA2(acc2[i][1], aa2[i], bb2[1]);
                    FFMA2(acc2[i][2], aa2[i], bb2[2]);
                    FFMA2(acc2[i][3], aa2[i], bb2[3]);
                    FFMA2(acc2[i][4], ao[i], bb2[0]);
                    FFMA2(acc2[i][5], ao[i], bb2[1]);
                    FFMA2(acc2[i][6], ao[i], bb2[2]);
                    FFMA2(acc2[i][7], ao[i], bb2[3]);
                }
            }
        }
    }

    float bv[8];
#pragma unroll
    for (int j = 0; j < 8; j++) bv[j] = bias[nb + tx * 8 + j];

    // acc2[i][0..3] -> row m=ty*8+2i ; acc2[i][4..7] -> row m=ty*8+2i+1
#pragma unroll
    for (int i = 0; i < 4; i++) {
#pragma unroll
        for (int half = 0; half < 2; half++) {
            int m    = mb + ty * 8 + 2 * i + half;
            int bidx = m >> 12;
            int tt   = m & (T_ - 1);
            float* op = g_igates + ((size_t)tt * B_ + bidx) * G_ + nb + tx * 8;
            const unsigned long long* ac = &acc2[i][half * 4];
            float2 p0 = unpack2(ac[0]), p1 = unpack2(ac[1]);
            float2 p2 = unpack2(ac[2]), p3 = unpack2(ac[3]);
            float4 v0 = make_float4(p0.x + bv[0], p0.y + bv[1], p1.x + bv[2], p1.y + bv[3]);
            float4 v1 = make_float4(p2.x + bv[4], p2.y + bv[5], p3.x + bv[6], p3.y + bv[7]);
            *(float4*)op       = v0;
            *(float4*)(op + 4) = v1;
        }
    }
}

// ---------------------------------------------------------------------------
// Cluster / DSMEM / mbarrier helpers
// ---------------------------------------------------------------------------
__device__ __forceinline__ uint32_t smem_u32(const void* p) {
    uint32_t a;
    asm("{ .reg .u64 t; cvta.to.shared.u64 t, %1; cvt.u32.u64 %0, t; }"
        : "=r"(a) : "l"(p));
    return a;
}
__device__ __forceinline__ uint32_t mapa_u32(uint32_t a, uint32_t rank) {
    uint32_t r;
    asm("mapa.shared::cluster.u32 %0, %1, %2;" : "=r"(r) : "r"(a), "r"(rank));
    return r;
}
__device__ __forceinline__ uint32_t ctarank() {
    uint32_t r;
    asm("mov.u32 %0, %%cluster_ctarank;" : "=r"(r));
    return r;
}
#define CLUSTER_SYNC() do { \
    asm volatile("barrier.cluster.arrive.aligned;" ::: "memory"); \
    asm volatile("barrier.cluster.wait.aligned;"   ::: "memory"); \
} while (0)

#define MBAR_INIT(a, c) \
    asm volatile("mbarrier.init.shared.b64 [%0], %1;" :: "r"(a), "r"(c) : "memory")
#define MBAR_EXPECT_TX(a, tx) \
    asm volatile("mbarrier.arrive.expect_tx.shared.b64 _, [%0], %1;" :: "r"(a), "r"(tx) : "memory")

// Remote 16B store with mbarrier tx completion.
#define ST_ASYNC_V4(addr, x, y, z, w, mbar) \
    asm volatile("st.async.shared::cluster.mbarrier::complete_tx::bytes.v4.b32 [%0], {%1,%2,%3,%4}, [%5];" \
                 :: "r"(addr), "r"(__float_as_uint(x)), "r"(__float_as_uint(y)), \
                    "r"(__float_as_uint(z)), "r"(__float_as_uint(w)), "r"(mbar) : "memory")

// cta-scope acquire: canonical for async-proxy data delivered into LOCAL smem.
__device__ __forceinline__ void mbar_wait(uint32_t addr, uint32_t phase) {
    uint32_t done;
    asm volatile(
        "{\n\t.reg .pred p;\n\t"
        "mbarrier.try_wait.parity.acquire.cta.shared::cta.b64 p, [%1], %2;\n\t"
        "selp.b32 %0, 1, 0, p;\n\t}"
        : "=r"(done) : "r"(addr), "r"(phase) : "memory");
    while (!done) {
        asm volatile(
            "{\n\t.reg .pred p;\n\t"
            "mbarrier.try_wait.parity.acquire.cta.shared::cta.b64 p, [%1], %2, 0x989680;\n\t"
            "selp.b32 %0, 1, 0, p;\n\t}"
            : "=r"(done) : "r"(addr), "r"(phase) : "memory");
    }
}

// MUFU-based activations (ex2/rcp approx: rel err ~2^-22)
__device__ __forceinline__ float fast_sigmoid(float x) {
    float e, r;
    asm("ex2.approx.f32 %0, %1;" : "=f"(e) : "f"(x * -1.442695040888963f));
    asm("rcp.approx.f32 %0, %1;" : "=f"(r) : "f"(1.f + e));
    return r;
}
__device__ __forceinline__ float fast_tanh(float x) {
    float e, r;
    asm("ex2.approx.f32 %0, %1;" : "=f"(e) : "f"(x * -2.885390081777927f));
    asm("rcp.approx.f32 %0, %1;" : "=f"(r) : "f"(1.f + e));
    return fmaf(2.f, r, -1.f);
}

// ---------------------------------------------------------------------------
// Kernel 2: GRU recurrence — EXACT structure of the 10966us best submission.
// 16 clusters x 8 CTAs, owner-partitioned weights, per-source bm-major h
// blocks fed by st.async.v4 (512B tx per source barrier). Re-arm of
// expect_tx immediately after bar.sync 2 and BEFORE sends (causal gating).
// ---------------------------------------------------------------------------
__global__ __launch_bounds__(768, 1) void gru_scan(
    const float* __restrict__ Whh,   // [G_, H_]
    const float* __restrict__ bn_g)  // [H_]
{
    __shared__ __align__(16) float hPf[2][1024];          // per-source bm-major blocks
    __shared__ __align__(16) float part[2][8 * 4 * 96];   // [buf][kc][bm][row]
    __shared__ __align__(8) unsigned long long mbars[16]; // [buf][src]

    const int tid   = threadIdx.x;
    const uint32_t crank = ctarank();
    const int bbase = (blockIdx.x >> 3) * 4;

    const int warp = tid >> 5, lane = tid & 31;
    const int kc = warp / 3;                 // k-chunk / source 0..7
    const int r  = (warp % 3) * 32 + lane;   // local row 0..95 (gate = r>>5)

    // Owner-partitioned weight rows: gate*256 + crank*32 + (r&31), f32x2 pairs
    unsigned long long w2[16];
    {
        const int grow = (r >> 5) * 256 + (int)crank * 32 + (r & 31);
        const ulonglong2* wr = reinterpret_cast<const ulonglong2*>(
            Whh + (size_t)grow * H_ + kc * 32);
#pragma unroll
        for (int i = 0; i < 8; i++) { ulonglong2 v = wr[i]; w2[2*i] = v.x; w2[2*i+1] = v.y; }
    }

    const uint32_t hP_base   = smem_u32(hPf);
    const uint32_t mbar_base = smem_u32(mbars);
    const uint32_t my_wait   = mbar_base + (uint32_t)kc * 8;  // + buf*64 per step

    // Gating thread (tid<128): h index crank*32+gj, batch gbm; h in register.
    const int gbm = tid >> 5, gj = tid & 31;
    float bnv = 0.f, hreg = 0.f;
    const float* igp = g_igates + (size_t)(bbase + gbm) * G_ + (int)crank * 32 + gj;
    if (tid < 128) bnv = bn_g[(int)crank * 32 + gj];

    // Send setup (gating lanes): lane gj handles quad c = gj>>2 to dests
    // d0 = gj&3 and d1 = d0+4. Dest float4 = hPf[buf'][crank*128+gbm*32+4c..].
    uint32_t send_a0 = 0, send_a1 = 0, send_m0 = 0, send_m1 = 0;
    if (tid < 128) {
        const uint32_t c  = (uint32_t)(gj >> 2);
        const uint32_t d0 = (uint32_t)(gj & 3), d1 = d0 + 4;
        uint32_t base = hP_base + (uint32_t)crank * 512 + (uint32_t)gbm * 128 + c * 16;
        send_a0 = mapa_u32(base, d0);
        send_a1 = mapa_u32(base, d1);
        send_m0 = mapa_u32(mbar_base + (uint32_t)crank * 8, d0);
        send_m1 = mapa_u32(mbar_base + (uint32_t)crank * 8, d1);
    }

    // Init barriers (1 arrival + tx), zero h buffer 0, prime buf1 expects.
    if (tid < 16) MBAR_INIT(mbar_base + tid * 8, 1);
    __syncthreads();
    if (tid < 8) MBAR_EXPECT_TX(mbar_base + 64 + tid * 8, 512);
    for (int i = tid; i < 1024; i += 768) hPf[0][i] = 0.f;
    __syncthreads();
    CLUSTER_SYNC();   // barriers + zeros visible before any sends

    for (int t = 0; t < T_; t++) {
        const int buf = t & 1;
        const uint32_t phase = (uint32_t)(((t >> 1) + (buf ^ 1)) & 1);

        // igates load for this step (independent of h; covered by wait+matvec)
        float ig_r = 0.f, ig_z = 0.f, ig_n = 0.f;
        if (tid < 128) {
            const float* p = igp + (size_t)t * (B_ * G_);
            ig_r = p[0]; ig_z = p[256]; ig_n = p[512];
        }

        // Wait only for this warp's source block
        if (t > 0) mbar_wait(my_wait + (uint32_t)buf * 64, phase);

        // Matvec: per c-iter 4x LDS.128 (one per batch) + 8 FFMA2
        unsigned long long a0 = 0ull, a1 = 0ull, a2 = 0ull, a3 = 0ull;
        {
            const ulonglong2* hv = reinterpret_cast<const ulonglong2*>(&hPf[buf][kc * 128]);
#pragma unroll
            for (int c = 0; c < 8; c++) {
                ulonglong2 u0 = hv[c];
                ulonglong2 u1 = hv[8 + c];
                ulonglong2 u2 = hv[16 + c];
                ulonglong2 u3 = hv[24 + c];
                FFMA2(a0, w2[2*c], u0.x); FFMA2(a0, w2[2*c+1], u0.y);
                FFMA2(a1, w2[2*c], u1.x); FFMA2(a1, w2[2*c+1], u1.y);
                FFMA2(a2, w2[2*c], u2.x); FFMA2(a2, w2[2*c+1], u2.y);
                FFMA2(a3, w2[2*c], u3.x); FFMA2(a3, w2[2*c+1], u3.y);
            }
        }
        {
            float2 f0 = unpack2(a0), f1 = unpack2(a1), f2 = unpack2(a2), f3 = unpack2(a3);
            float* pb = part[buf] + kc * 384;
            pb[      r] = f0.x + f0.y;   // conflict-free: bank = lane
            pb[ 96 + r] = f1.x + f1.y;
            pb[192 + r] = f2.x + f2.y;
            pb[288 + r] = f3.x + f3.y;
        }

        if (warp >= 4) {
            asm volatile("bar.arrive 2, 768;" ::: "memory");
            continue;
        }

        // Gating warps: wait for all partials
        asm volatile("bar.sync 2, 768;" ::: "memory");

        // Re-arm barriers[buf] for step t+2 BEFORE our sends: warp-0 program
        // order makes re-arm causally precede all inbound t+2-phase traffic.
        if (tid < 8) MBAR_EXPECT_TX(mbar_base + (uint32_t)buf * 64 + (uint32_t)tid * 8, 512);

        // Reduce 8 k-chunks for rows gj / 32+gj / 64+gj of batch gbm
        float hr = 0.f, hz = 0.f, hn = 0.f;
        {
            const float* pb = part[buf] + gbm * 96 + gj;
#pragma unroll
            for (int q = 0; q < 8; q++) {
                hr += pb[q * 384];
                hz += pb[q * 384 + 32];
                hn += pb[q * 384 + 64];
            }
        }
        float rr = fast_sigmoid(ig_r + hr);
        float zz = fast_sigmoid(ig_z + hz);
        float nn = fast_tanh(ig_n + rr * (hn + bnv));
        hreg = nn + zz * (hreg - nn);

        if (t == T_ - 1) {
            g_hfinal[(bbase + gbm) * H_ + (int)crank * 32 + gj] = hreg;
        } else {
            // Shuffle-pack quad (gj&~3 .. +3) and send straight from registers.
            const int qb = gj & ~3;
            float v0 = __shfl_sync(0xffffffffu, hreg, qb + 0);
            float v1 = __shfl_sync(0xffffffffu, hreg, qb + 1);
            float v2 = __shfl_sync(0xffffffffu, hreg, qb + 2);
            float v3 = __shfl_sync(0xffffffffu, hreg, qb + 3);
            const uint32_t off = (uint32_t)(buf ^ 1) * 4096;
            const uint32_t mof = (uint32_t)(buf ^ 1) * 64;
            ST_ASYNC_V4(send_a0 + off, v0, v1, v2, v3, send_m0 + mof);
            ST_ASYNC_V4(send_a1 + off, v0, v1, v2, v3, send_m1 + mof);
        }
    }

    CLUSTER_SYNC();  // no CTA exits while peers' inbound stores may reference it
}

// ---------------------------------------------------------------------------
// Kernel 3: out = h_final @ w_proj^T + b_proj
// ---------------------------------------------------------------------------
__global__ __launch_bounds__(128) void proj_kernel(
    const float* __restrict__ Wp,
    const float* __restrict__ bp,
    float* __restrict__ out)
{
    __shared__ float hs[H_];
    int b = blockIdx.x;
    for (int k = threadIdx.x; k < H_; k += 128) hs[k] = g_hfinal[b * H_ + k];
    __syncthreads();
    int c = threadIdx.x;
    float acc = bp[c];
    const float* wr = Wp + (size_t)c * H_;
#pragma unroll 8
    for (int k = 0; k < H_; k++) acc = fmaf(hs[k], wr[k], acc);
    out[b * C_ + c] = acc;
}

// ---------------------------------------------------------------------------
// Launch: strictly serial on one stream.
// ---------------------------------------------------------------------------
extern "C" void kernel_launch(void* const* d_in, const int* in_sizes, int n_in,
                              void* d_out, int out_size)
{
    const float* x      = (const float*)d_in[0];
    const float* w_ih   = (const float*)d_in[1];
    const float* w_hh   = (const float*)d_in[2];
    const float* b      = (const float*)d_in[3];
    const float* bn     = (const float*)d_in[4];
    const float* w_proj = (const float*)d_in[5];
    const float* b_proj = (const float*)d_in[6];
    float* out = (float*)d_out;

    dim3 g1((B_ * T_) / 128, G_ / 128);
    igates_gemm<<<g1, 256>>>(x, w_ih, b);

    {
        cudaLaunchConfig_t cfg = {};
        cfg.gridDim  = dim3(128, 1, 1);
        cfg.blockDim = dim3(768, 1, 1);
        cfg.dynamicSmemBytes = 0;
        cfg.stream = 0;
        cudaLaunchAttribute attr[1];
        attr[0].id = cudaLaunchAttributeClusterDimension;
        attr[0].val.clusterDim.x = 8;
        attr[0].val.clusterDim.y = 1;
        attr[0].val.clusterDim.z = 1;
        cfg.attrs = attr;
        cfg.numAttrs = 1;
        cudaLaunchKernelEx(&cfg, gru_scan, w_hh, bn);
    }

    proj_kernel<<<B_, 128>>>(w_proj, b_proj, out);
}

// round 17
// speedup vs baseline: 1.8335x; 1.0957x over previous
#include <cuda_runtime.h>
#include <cstdint>
#include <math.h>

// Problem constants
#define B_   64
#define T_   4096
#define D_   128
#define H_   256
#define G_   768   // 3*H
#define C_   128

__device__ float g_igates[(size_t)T_ * B_ * G_];
__device__ float g_hfinal[B_ * H_];

// Packed fp32x2 FMA (Blackwell)
#define FFMA2(acc, a, b) \
    asm("fma.rn.f32x2 %0, %1, %2, %0;" : "+l"(acc) : "l"(a), "l"(b))
#define PACK2(out, lo, hi) \
    asm("mov.b64 %0, {%1, %2};" : "=l"(out) : "f"(lo), "f"(hi))

__device__ __forceinline__ float2 unpack2(unsigned long long v) {
    float2 f;
    asm("mov.b64 {%0, %1}, %2;" : "=f"(f.x), "=f"(f.y) : "l"(v));
    return f;
}

// ---------------------------------------------------------------------------
// Kernel 1: igates = x @ w_ih^T + b   (f32x2 sgemm, 128x128x16 tiles)
// R7/record version: best measured (1.22us slice, 106 regs, 16KB smem,
// occ 24.5%). At the 6-wavefront/k-step SMEM floor for this tiling —
// proven invariant under warp remaps (R15/R12 post-mortems).
// ---------------------------------------------------------------------------
__global__ __launch_bounds__(256) void igates_gemm(
    const float* __restrict__ X,
    const float* __restrict__ W,
    const float* __restrict__ bias)
{
    __shared__ float As[16][128];
    __shared__ float Bs[16][128];

    const int tid = threadIdx.x;
    const int mb  = blockIdx.x * 128;
    const int nb  = blockIdx.y * 128;
    const int tx  = tid & 15;
    const int ty  = tid >> 4;
    const int lq  = tid & 3;
    const int lm  = tid >> 2;

    unsigned long long acc2[8][4];
#pragma unroll
    for (int i = 0; i < 8; i++)
#pragma unroll
        for (int j = 0; j < 4; j++) acc2[i][j] = 0ull;

    const float* Xp0 = X + (size_t)(mb + lm) * D_ + 4 * lq;
    const float* Xp1 = Xp0 + (size_t)64 * D_;
    const float* Wp0 = W + (size_t)(nb + lm) * D_ + 4 * lq;
    const float* Wp1 = Wp0 + (size_t)64 * D_;

#pragma unroll
    for (int kt = 0; kt < D_; kt += 16) {
        float4 a0 = *(const float4*)(Xp0 + kt);
        float4 a1 = *(const float4*)(Xp1 + kt);
        float4 b0 = *(const float4*)(Wp0 + kt);
        float4 b1 = *(const float4*)(Wp1 + kt);
        __syncthreads();
        As[4*lq+0][lm]    = a0.x; As[4*lq+1][lm]    = a0.y; As[4*lq+2][lm]    = a0.z; As[4*lq+3][lm]    = a0.w;
        As[4*lq+0][lm+64] = a1.x; As[4*lq+1][lm+64] = a1.y; As[4*lq+2][lm+64] = a1.z; As[4*lq+3][lm+64] = a1.w;
        Bs[4*lq+0][lm]    = b0.x; Bs[4*lq+1][lm]    = b0.y; Bs[4*lq+2][lm]    = b0.z; Bs[4*lq+3][lm]    = b0.w;
        Bs[4*lq+0][lm+64] = b1.x; Bs[4*lq+1][lm+64] = b1.y; Bs[4*lq+2][lm+64] = b1.z; Bs[4*lq+3][lm+64] = b1.w;
        __syncthreads();
#pragma unroll
        for (int k = 0; k < 16; k++) {
            float a[8];
            unsigned long long bb2[4];
            *(float4*)&a[0] = *(const float4*)&As[k][ty * 8];
            *(float4*)&a[4] = *(const float4*)&As[k][ty * 8 + 4];
            {
                ulonglong2 q0 = *(const ulonglong2*)&Bs[k][tx * 8];
                ulonglong2 q1 = *(const ulonglong2*)&Bs[k][tx * 8 + 4];
                bb2[0] = q0.x; bb2[1] = q0.y; bb2[2] = q1.x; bb2[3] = q1.y;
            }
#pragma unroll
            for (int i = 0; i < 8; i++) {
                unsigned long long ai;
                PACK2(ai, a[i], a[i]);
                FFMA2(acc2[i][0], ai, bb2[0]);
                FFMA2(acc2[i][1], ai, bb2[1]);
                FFMA2(acc2[i][2], ai, bb2[2]);
                FFMA2(acc2[i][3], ai, bb2[3]);
            }
        }
    }

    float bv[8];
#pragma unroll
    for (int j = 0; j < 8; j++) bv[j] = bias[nb + tx * 8 + j];

#pragma unroll
    for (int i = 0; i < 8; i++) {
        int m    = mb + ty * 8 + i;
        int bidx = m >> 12;
        int tt   = m & (T_ - 1);
        float* op = g_igates + ((size_t)tt * B_ + bidx) * G_ + nb + tx * 8;
        float2 p0 = unpack2(acc2[i][0]), p1 = unpack2(acc2[i][1]);
        float2 p2 = unpack2(acc2[i][2]), p3 = unpack2(acc2[i][3]);
        float4 v0 = make_float4(p0.x + bv[0], p0.y + bv[1], p1.x + bv[2], p1.y + bv[3]);
        float4 v1 = make_float4(p2.x + bv[4], p2.y + bv[5], p3.x + bv[6], p3.y + bv[7]);
        *(float4*)op       = v0;
        *(float4*)(op + 4) = v1;
    }
}

// ---------------------------------------------------------------------------
// Cluster / DSMEM / mbarrier helpers
// ---------------------------------------------------------------------------
__device__ __forceinline__ uint32_t smem_u32(const void* p) {
    uint32_t a;
    asm("{ .reg .u64 t; cvta.to.shared.u64 t, %1; cvt.u32.u64 %0, t; }"
        : "=r"(a) : "l"(p));
    return a;
}
__device__ __forceinline__ uint32_t mapa_u32(uint32_t a, uint32_t rank) {
    uint32_t r;
    asm("mapa.shared::cluster.u32 %0, %1, %2;" : "=r"(r) : "r"(a), "r"(rank));
    return r;
}
__device__ __forceinline__ uint32_t ctarank() {
    uint32_t r;
    asm("mov.u32 %0, %%cluster_ctarank;" : "=r"(r));
    return r;
}
#define CLUSTER_SYNC() do { \
    asm volatile("barrier.cluster.arrive.aligned;" ::: "memory"); \
    asm volatile("barrier.cluster.wait.aligned;"   ::: "memory"); \
} while (0)

#define MBAR_INIT(a, c) \
    asm volatile("mbarrier.init.shared.b64 [%0], %1;" :: "r"(a), "r"(c) : "memory")
#define MBAR_EXPECT_TX(a, tx) \
    asm volatile("mbarrier.arrive.expect_tx.shared.b64 _, [%0], %1;" :: "r"(a), "r"(tx) : "memory")

// Remote 16B store with mbarrier tx completion.
#define ST_ASYNC_V4(addr, x, y, z, w, mbar) \
    asm volatile("st.async.shared::cluster.mbarrier::complete_tx::bytes.v4.b32 [%0], {%1,%2,%3,%4}, [%5];" \
                 :: "r"(addr), "r"(__float_as_uint(x)), "r"(__float_as_uint(y)), \
                    "r"(__float_as_uint(z)), "r"(__float_as_uint(w)), "r"(mbar) : "memory")

// cta-scope acquire: canonical for async-proxy data delivered into LOCAL smem.
__device__ __forceinline__ void mbar_wait(uint32_t addr, uint32_t phase) {
    uint32_t done;
    asm volatile(
        "{\n\t.reg .pred p;\n\t"
        "mbarrier.try_wait.parity.acquire.cta.shared::cta.b64 p, [%1], %2;\n\t"
        "selp.b32 %0, 1, 0, p;\n\t}"
        : "=r"(done) : "r"(addr), "r"(phase) : "memory");
    while (!done) {
        asm volatile(
            "{\n\t.reg .pred p;\n\t"
            "mbarrier.try_wait.parity.acquire.cta.shared::cta.b64 p, [%1], %2, 0x989680;\n\t"
            "selp.b32 %0, 1, 0, p;\n\t}"
            : "=r"(done) : "r"(addr), "r"(phase) : "memory");
    }
}

// MUFU-based activations (ex2/rcp approx: rel err ~2^-22)
__device__ __forceinline__ float fast_sigmoid(float x) {
    float e, r;
    asm("ex2.approx.f32 %0, %1;" : "=f"(e) : "f"(x * -1.442695040888963f));
    asm("rcp.approx.f32 %0, %1;" : "=f"(r) : "f"(1.f + e));
    return r;
}
__device__ __forceinline__ float fast_tanh(float x) {
    float e, r;
    asm("ex2.approx.f32 %0, %1;" : "=f"(e) : "f"(x * -2.885390081777927f));
    asm("rcp.approx.f32 %0, %1;" : "=f"(r) : "f"(1.f + e));
    return fmaf(2.f, r, -1.f);
}

// ---------------------------------------------------------------------------
// Kernel 2: GRU recurrence — the record structure (10966us). 16 clusters x
// 8 CTAs, owner-partitioned weights, per-source bm-major h blocks fed by
// st.async.v4 (512B tx per source barrier). Re-arm of expect_tx immediately
// after bar.sync 2 and BEFORE sends (causal gating; R8 lesson).
// Micro-edits vs record: running igates pointer (no per-step 64-bit mul),
// hoisted per-buf wait addresses.
// ---------------------------------------------------------------------------
__global__ __launch_bounds__(768, 1) void gru_scan(
    const float* __restrict__ Whh,   // [G_, H_]
    const float* __restrict__ bn_g)  // [H_]
{
    __shared__ __align__(16) float hPf[2][1024];          // per-source bm-major blocks
    __shared__ __align__(16) float part[2][8 * 4 * 96];   // [buf][kc][bm][row]
    __shared__ __align__(8) unsigned long long mbars[16]; // [buf][src]

    const int tid   = threadIdx.x;
    const uint32_t crank = ctarank();
    const int bbase = (blockIdx.x >> 3) * 4;

    const int warp = tid >> 5, lane = tid & 31;
    const int kc = warp / 3;                 // k-chunk / source 0..7
    const int r  = (warp % 3) * 32 + lane;   // local row 0..95 (gate = r>>5)

    // Owner-partitioned weight rows: gate*256 + crank*32 + (r&31), f32x2 pairs
    unsigned long long w2[16];
    {
        const int grow = (r >> 5) * 256 + (int)crank * 32 + (r & 31);
        const ulonglong2* wr = reinterpret_cast<const ulonglong2*>(
            Whh + (size_t)grow * H_ + kc * 32);
#pragma unroll
        for (int i = 0; i < 8; i++) { ulonglong2 v = wr[i]; w2[2*i] = v.x; w2[2*i+1] = v.y; }
    }

    const uint32_t hP_base   = smem_u32(hPf);
    const uint32_t mbar_base = smem_u32(mbars);
    const uint32_t wait0     = mbar_base + (uint32_t)kc * 8;   // buf 0
    const uint32_t wait1     = wait0 + 64;                     // buf 1

    // Gating thread (tid<128): h index crank*32+gj, batch gbm; h in register.
    const int gbm = tid >> 5, gj = tid & 31;
    float bnv = 0.f, hreg = 0.f;
    const float* igp = g_igates + (size_t)(bbase + gbm) * G_ + (int)crank * 32 + gj;
    if (tid < 128) bnv = bn_g[(int)crank * 32 + gj];

    // Send setup (gating lanes): lane gj handles quad c = gj>>2 to dests
    // d0 = gj&3 and d1 = d0+4. Dest float4 = hPf[buf'][crank*128+gbm*32+4c..].
    uint32_t send_a0 = 0, send_a1 = 0, send_m0 = 0, send_m1 = 0;
    if (tid < 128) {
        const uint32_t c  = (uint32_t)(gj >> 2);
        const uint32_t d0 = (uint32_t)(gj & 3), d1 = d0 + 4;
        uint32_t base = hP_base + (uint32_t)crank * 512 + (uint32_t)gbm * 128 + c * 16;
        send_a0 = mapa_u32(base, d0);
        send_a1 = mapa_u32(base, d1);
        send_m0 = mapa_u32(mbar_base + (uint32_t)crank * 8, d0);
        send_m1 = mapa_u32(mbar_base + (uint32_t)crank * 8, d1);
    }

    // Init barriers (1 arrival + tx), zero h buffer 0, prime buf1 expects.
    if (tid < 16) MBAR_INIT(mbar_base + tid * 8, 1);
    __syncthreads();
    if (tid < 8) MBAR_EXPECT_TX(mbar_base + 64 + tid * 8, 512);
    for (int i = tid; i < 1024; i += 768) hPf[0][i] = 0.f;
    __syncthreads();
    CLUSTER_SYNC();   // barriers + zeros visible before any sends

    for (int t = 0; t < T_; t++) {
        const int buf = t & 1;
        const uint32_t phase = (uint32_t)(((t >> 1) + (buf ^ 1)) & 1);

        // igates load for this step (running pointer; covered by wait+matvec)
        float ig_r = 0.f, ig_z = 0.f, ig_n = 0.f;
        if (tid < 128) {
            ig_r = igp[0]; ig_z = igp[256]; ig_n = igp[512];
        }

        // Wait only for this warp's source block
        if (t > 0) mbar_wait(buf ? wait1 : wait0, phase);

        // Matvec: per c-iter 4x LDS.128 (one per batch) + 8 FFMA2
        unsigned long long a0 = 0ull, a1 = 0ull, a2 = 0ull, a3 = 0ull;
        {
            const ulonglong2* hv = reinterpret_cast<const ulonglong2*>(&hPf[buf][kc * 128]);
#pragma unroll
            for (int c = 0; c < 8; c++) {
                ulonglong2 u0 = hv[c];
                ulonglong2 u1 = hv[8 + c];
                ulonglong2 u2 = hv[16 + c];
                ulonglong2 u3 = hv[24 + c];
                FFMA2(a0, w2[2*c], u0.x); FFMA2(a0, w2[2*c+1], u0.y);
                FFMA2(a1, w2[2*c], u1.x); FFMA2(a1, w2[2*c+1], u1.y);
                FFMA2(a2, w2[2*c], u2.x); FFMA2(a2, w2[2*c+1], u2.y);
                FFMA2(a3, w2[2*c], u3.x); FFMA2(a3, w2[2*c+1], u3.y);
            }
        }
        {
            float2 f0 = unpack2(a0), f1 = unpack2(a1), f2 = unpack2(a2), f3 = unpack2(a3);
            float* pb = part[buf] + kc * 384;
            pb[      r] = f0.x + f0.y;   // conflict-free: bank = lane
            pb[ 96 + r] = f1.x + f1.y;
            pb[192 + r] = f2.x + f2.y;
            pb[288 + r] = f3.x + f3.y;
        }

        if (warp >= 4) {
            asm volatile("bar.arrive 2, 768;" ::: "memory");
            continue;
        }

        // Gating warps: wait for all partials
        asm volatile("bar.sync 2, 768;" ::: "memory");

        // Re-arm barriers[buf] for step t+2 BEFORE our sends: warp-0 program
        // order makes re-arm causally precede all inbound t+2-phase traffic.
        if (tid < 8) MBAR_EXPECT_TX(mbar_base + (uint32_t)buf * 64 + (uint32_t)tid * 8, 512);

        // Reduce 8 k-chunks for rows gj / 32+gj / 64+gj of batch gbm
        float hr = 0.f, hz = 0.f, hn = 0.f;
        {
            const float* pb = part[buf] + gbm * 96 + gj;
#pragma unroll
            for (int q = 0; q < 8; q++) {
                hr += pb[q * 384];
                hz += pb[q * 384 + 32];
                hn += pb[q * 384 + 64];
            }
        }
        float rr = fast_sigmoid(ig_r + hr);
        float zz = fast_sigmoid(ig_z + hz);
        float nn = fast_tanh(ig_n + rr * (hn + bnv));
        hreg = nn + zz * (hreg - nn);
        igp += B_ * G_;   // advance running igates pointer

        if (t == T_ - 1) {
            g_hfinal[(bbase + gbm) * H_ + (int)crank * 32 + gj] = hreg;
        } else {
            // Shuffle-pack quad (gj&~3 .. +3) and send straight from registers.
            const int qb = gj & ~3;
            float v0 = __shfl_sync(0xffffffffu, hreg, qb + 0);
            float v1 = __shfl_sync(0xffffffffu, hreg, qb + 1);
            float v2 = __shfl_sync(0xffffffffu, hreg, qb + 2);
            float v3 = __shfl_sync(0xffffffffu, hreg, qb + 3);
            const uint32_t off = (uint32_t)(buf ^ 1) * 4096;
            const uint32_t mof = (uint32_t)(buf ^ 1) * 64;
            ST_ASYNC_V4(send_a0 + off, v0, v1, v2, v3, send_m0 + mof);
            ST_ASYNC_V4(send_a1 + off, v0, v1, v2, v3, send_m1 + mof);
        }
    }

    CLUSTER_SYNC();  // no CTA exits while peers' inbound stores may reference it
}

// ---------------------------------------------------------------------------
// Kernel 3: out = h_final @ w_proj^T + b_proj
// ---------------------------------------------------------------------------
__global__ __launch_bounds__(128) void proj_kernel(
    const float* __restrict__ Wp,
    const float* __restrict__ bp,
    float* __restrict__ out)
{
    __shared__ float hs[H_];
    int b = blockIdx.x;
    for (int k = threadIdx.x; k < H_; k += 128) hs[k] = g_hfinal[b * H_ + k];
    __syncthreads();
    int c = threadIdx.x;
    float acc = bp[c];
    const float* wr = Wp + (size_t)c * H_;
#pragma unroll 8
    for (int k = 0; k < H_; k++) acc = fmaf(hs[k], wr[k], acc);
    out[b * C_ + c] = acc;
}

// ---------------------------------------------------------------------------
// Launch: strictly serial on one stream.
// ---------------------------------------------------------------------------
extern "C" void kernel_launch(void* const* d_in, const int* in_sizes, int n_in,
                              void* d_out, int out_size)
{
    const float* x      = (const float*)d_in[0];
    const float* w_ih   = (const float*)d_in[1];
    const float* w_hh   = (const float*)d_in[2];
    const float* b      = (const float*)d_in[3];
    const float* bn     = (const float*)d_in[4];
    const float* w_proj = (const float*)d_in[5];
    const float* b_proj = (const float*)d_in[6];
    float* out = (float*)d_out;

    dim3 g1((B_ * T_) / 128, G_ / 128);
    igates_gemm<<<g1, 256>>>(x, w_ih, b);

    {
        cudaLaunchConfig_t cfg = {};
        cfg.gridDim  = dim3(128, 1, 1);
        cfg.blockDim = dim3(768, 1, 1);
        cfg.dynamicSmemBytes = 0;
        cfg.stream = 0;
        cudaLaunchAttribute attr[1];
        attr[0].id = cudaLaunchAttributeClusterDimension;
        attr[0].val.clusterDim.x = 8;
        attr[0].val.clusterDim.y = 1;
        attr[0].val.clusterDim.z = 1;
        cfg.attrs = attr;
        cfg.numAttrs = 1;
        cudaLaunchKernelEx(&cfg, gru_scan, w_hh, bn);
    }

    proj_kernel<<<B_, 128>>>(w_proj, b_proj, out);
}